// round 2
// baseline (speedup 1.0000x reference)
#include <cuda_runtime.h>

#define NPTS   50000
#define KNN    16
#define CH     128
#define CSH    16
#define MROWS  (NPTS*KNN)
#define BN_EPS 1e-5f

// ---------------- device scratch (no allocations allowed) ----------------
__device__ __align__(16) float g_z[NPTS*CSH];
__device__ __align__(16) float g_num[NPTS*CSH];
__device__ float g_stats[6];   // [0..2] sum(h), [3..5] sum(h^2)
__device__ float g_M[3*CSH];   // folded p-path matrix (3 x 16)
__device__ float g_Bc[CSH];    // folded bias for s
__device__ float g_wf[9];      // BN-folded W_p1 (gamma*rstd absorbed)
__device__ float g_gb[3];      // BN shift (beta - mu*scale)

// ---------------- init: zero accumulators ----------------
__global__ void init_kernel() {
    int i = blockIdx.x*blockDim.x + threadIdx.x;
    if (i < NPTS*CSH) { g_z[i] = 0.f; g_num[i] = 0.f; }
    if (i < 6) g_stats[i] = 0.f;
}

// ---------------- BN stats over h = p_r @ W_p1^T ----------------
__global__ void stats_kernel(const float* __restrict__ p_r,
                             const float* __restrict__ W_p1) {
    float w0=W_p1[0],w1=W_p1[1],w2=W_p1[2],w3=W_p1[3],w4=W_p1[4],
          w5=W_p1[5],w6=W_p1[6],w7=W_p1[7],w8=W_p1[8];
    float s0=0,s1=0,s2=0,q0=0,q1=0,q2=0;
    int stride = gridDim.x*blockDim.x;
    for (int i = blockIdx.x*blockDim.x + threadIdx.x; i < MROWS; i += stride) {
        float p0=p_r[3*i+0], p1=p_r[3*i+1], p2=p_r[3*i+2];
        float h0 = p0*w0 + p1*w1 + p2*w2;
        float h1 = p0*w3 + p1*w4 + p2*w5;
        float h2 = p0*w6 + p1*w7 + p2*w8;
        s0+=h0; q0+=h0*h0; s1+=h1; q1+=h1*h1; s2+=h2; q2+=h2*h2;
    }
    #pragma unroll
    for (int o=16;o>0;o>>=1){
        s0+=__shfl_down_sync(0xffffffffu,s0,o);
        s1+=__shfl_down_sync(0xffffffffu,s1,o);
        s2+=__shfl_down_sync(0xffffffffu,s2,o);
        q0+=__shfl_down_sync(0xffffffffu,q0,o);
        q1+=__shfl_down_sync(0xffffffffu,q1,o);
        q2+=__shfl_down_sync(0xffffffffu,q2,o);
    }
    __shared__ float red[8][6];
    int wid = threadIdx.x>>5, lid = threadIdx.x&31;
    if (lid==0){ red[wid][0]=s0; red[wid][1]=s1; red[wid][2]=s2;
                 red[wid][3]=q0; red[wid][4]=q1; red[wid][5]=q2; }
    __syncthreads();
    if (threadIdx.x < 6) {
        float a = 0.f;
        #pragma unroll
        for (int w=0; w<8; w++) a += red[w][threadIdx.x];
        atomicAdd(&g_stats[threadIdx.x], a);
    }
}

// ---------------- fold constants: BN, M = W_p2^T @ W_lin_p^T, biases ----------------
__global__ void consts_kernel(const float* __restrict__ W_lin,
                              const float* __restrict__ b_lin,
                              const float* __restrict__ W_p2,
                              const float* __restrict__ b_p2,
                              const float* __restrict__ W_p1,
                              const float* __restrict__ gamma,
                              const float* __restrict__ beta) {
    int tid = threadIdx.x;
    if (tid < 3) {
        float inv = 1.f / (float)MROWS;
        float mu  = g_stats[tid] * inv;
        float var = g_stats[3+tid] * inv - mu*mu;
        float gs  = gamma[tid] * rsqrtf(var + BN_EPS);
        g_gb[tid] = beta[tid] - mu*gs;
        #pragma unroll
        for (int c=0;c<3;c++) g_wf[tid*3+c] = gs * W_p1[tid*3+c];
    }
    if (tid < 48) {
        int a = tid >> 4, j = tid & 15;
        float m = 0.f;
        for (int c=0;c<CH;c++) m += W_p2[c*3+a] * W_lin[j*256+c];
        g_M[a*CSH + j] = m;
    }
    if (tid >= 48 && tid < 64) {
        int j = tid - 48;
        float b = b_lin[j];
        for (int c=0;c<CH;c++) b += b_p2[c] * W_lin[j*256+c];
        g_Bc[j] = b;
    }
}

// ---------------- fused main kernel ----------------
struct SmemT {
    float As[128][132];   // x_knn tile, padded (row stride 132 floats)
    float Bs[128][36];    // weights k-major: col<16 -> W_lin[:,128:], col>=16 -> W_x
    float es[128][16];    // exp(s) exchange
    float hs[128][4];     // BN'd relu'd h per row
    int   is[128];        // segment index per row
    float Ms[3][16];
    float Bc[16];
    float bx[16];
    float wf[12];
    float gb[4];
};

__global__ void __launch_bounds__(256, 2) main_kernel(
    const float* __restrict__ x_knn,
    const int*   __restrict__ knn_idx,
    const float* __restrict__ p_r,
    const float* __restrict__ W_lin,
    const float* __restrict__ W_x,
    const float* __restrict__ b_x)
{
    extern __shared__ char smem_raw[];
    SmemT& sm = *reinterpret_cast<SmemT*>(smem_raw);
    const int tid  = threadIdx.x;
    const int base = blockIdx.x * 128;

    // stage A tile (coalesced float4): 4096 float4, 16 per thread
    const float4* src = reinterpret_cast<const float4*>(x_knn) + (size_t)base * 32;
    #pragma unroll
    for (int i=0;i<16;i++){
        int q = i*256 + tid;
        float4 v = src[q];
        *reinterpret_cast<float4*>(&sm.As[q>>5][(q&31)*4]) = v;
    }
    // stage B weights k-major: 4096 floats, 16 per thread
    #pragma unroll
    for (int i=0;i<16;i++){
        int q = i*256 + tid;
        int col = q>>7, k = q&127;
        sm.Bs[k][col] = (col < CSH) ? W_lin[col*256 + 128 + k]
                                    : W_x[(col-CSH)*CH + k];
    }
    if (tid < 48)       sm.Ms[tid>>4][tid&15] = g_M[tid];
    else if (tid < 64)  sm.Bc[tid-48] = g_Bc[tid-48];
    else if (tid < 80)  sm.bx[tid-64] = b_x[tid-64];
    else if (tid < 89)  sm.wf[tid-80] = g_wf[tid-80];
    else if (tid < 92)  sm.gb[tid-89] = g_gb[tid-89];
    if (tid < 128) sm.is[tid] = knn_idx[base + tid];

    // per-row BN'd relu'd h (3 values) -- needs wf/gb, so compute after they land
    __syncthreads();
    if (tid < 128) {
        int r = base + tid;
        float p0 = p_r[3*r+0], p1 = p_r[3*r+1], p2 = p_r[3*r+2];
        #pragma unroll
        for (int a=0;a<3;a++){
            float h = p0*sm.wf[a*3+0] + p1*sm.wf[a*3+1] + p2*sm.wf[a*3+2] + sm.gb[a];
            sm.hs[tid][a] = fmaxf(h, 0.f);
        }
    }
    __syncthreads();

    // register-tiled GEMM: C[128 x 32] = A[128 x 128] * B[128 x 32], f32x2 packed
    // thread tile: 2 rows (rg, rg+64) x 8 cols (4 packed u64)
    const int cg = tid & 3;    // col group: 8 cols each (0,1 -> s; 2,3 -> v)
    const int rg = tid >> 2;   // row group 0..63: rows rg, rg+64
    unsigned long long acc[2][4];
    #pragma unroll
    for (int r=0;r<2;r++)
        #pragma unroll
        for (int c=0;c<4;c++) acc[r][c] = 0ull;

    #pragma unroll 4
    for (int k4=0;k4<32;k4++){
        float4 av[2];
        #pragma unroll
        for (int r=0;r<2;r++)
            av[r] = *reinterpret_cast<const float4*>(&sm.As[rg + 64*r][k4*4]);
        #pragma unroll
        for (int kk=0;kk<4;kk++){
            ulonglong2 b01 = *reinterpret_cast<const ulonglong2*>(&sm.Bs[k4*4+kk][8*cg]);
            ulonglong2 b23 = *reinterpret_cast<const ulonglong2*>(&sm.Bs[k4*4+kk][8*cg+4]);
            #pragma unroll
            for (int r=0;r<2;r++){
                float a = (kk==0) ? av[r].x : (kk==1) ? av[r].y : (kk==2) ? av[r].z : av[r].w;
                unsigned long long aa;
                asm("mov.b64 %0, {%1, %1};" : "=l"(aa) : "r"(__float_as_uint(a)));
                asm("fma.rn.f32x2 %0, %1, %2, %0;" : "+l"(acc[r][0]) : "l"(aa), "l"(b01.x));
                asm("fma.rn.f32x2 %0, %1, %2, %0;" : "+l"(acc[r][1]) : "l"(aa), "l"(b01.y));
                asm("fma.rn.f32x2 %0, %1, %2, %0;" : "+l"(acc[r][2]) : "l"(aa), "l"(b23.x));
                asm("fma.rn.f32x2 %0, %1, %2, %0;" : "+l"(acc[r][3]) : "l"(aa), "l"(b23.y));
            }
        }
    }

    float out2[2][8];
    #pragma unroll
    for (int r=0;r<2;r++)
        #pragma unroll
        for (int c=0;c<4;c++){
            out2[r][2*c]   = __uint_as_float((unsigned)(acc[r][c] & 0xffffffffull));
            out2[r][2*c+1] = __uint_as_float((unsigned)(acc[r][c] >> 32));
        }

    // epilogue: s-threads produce e=exp(relu(s)) and scatter z; v-threads scatter num
    if (cg < 2) {
        const int jb = 8*cg;
        #pragma unroll
        for (int r=0;r<2;r++){
            int row = rg + 64*r;
            float h0 = sm.hs[row][0], h1 = sm.hs[row][1], h2 = sm.hs[row][2];
            float e[8];
            #pragma unroll
            for (int c=0;c<8;c++){
                int j = jb + c;
                float sv = out2[r][c] + sm.Bc[j]
                         + h0*sm.Ms[0][j] + h1*sm.Ms[1][j] + h2*sm.Ms[2][j];
                e[c] = __expf(fmaxf(sv, 0.f));
                sm.es[row][j] = e[c];
            }
            float* zp = &g_z[sm.is[row]*CSH + jb];
            asm volatile("red.global.add.v4.f32 [%0], {%1,%2,%3,%4};"
                         :: "l"(zp),   "f"(e[0]), "f"(e[1]), "f"(e[2]), "f"(e[3]) : "memory");
            asm volatile("red.global.add.v4.f32 [%0], {%1,%2,%3,%4};"
                         :: "l"(zp+4), "f"(e[4]), "f"(e[5]), "f"(e[6]), "f"(e[7]) : "memory");
        }
    } else {
        const int jb = 8*(cg-2);
        #pragma unroll
        for (int r=0;r<2;r++)
            #pragma unroll
            for (int c=0;c<8;c++)
                out2[r][c] = fmaxf(out2[r][c] + sm.bx[jb+c], 0.f);
    }
    __syncthreads();
    if (cg >= 2) {
        const int jb = 8*(cg-2);
        #pragma unroll
        for (int r=0;r<2;r++){
            int row = rg + 64*r;
            float w[8];
            #pragma unroll
            for (int c=0;c<8;c++) w[c] = out2[r][c] * sm.es[row][jb+c];
            float* np = &g_num[sm.is[row]*CSH + jb];
            asm volatile("red.global.add.v4.f32 [%0], {%1,%2,%3,%4};"
                         :: "l"(np),   "f"(w[0]), "f"(w[1]), "f"(w[2]), "f"(w[3]) : "memory");
            asm volatile("red.global.add.v4.f32 [%0], {%1,%2,%3,%4};"
                         :: "l"(np+4), "f"(w[4]), "f"(w[5]), "f"(w[6]), "f"(w[7]) : "memory");
        }
    }
}

// ---------------- output: x + tile(num/z, 8) ----------------
__global__ void out_kernel(const float* __restrict__ x, float* __restrict__ out) {
    int i = blockIdx.x*blockDim.x + threadIdx.x;
    if (i >= NPTS*32) return;
    int n = i >> 5, q = i & 31;
    int jb = (q & 3) * 4;               // (4q) % 16
    float4 xv = reinterpret_cast<const float4*>(x)[i];
    float4 zv = *reinterpret_cast<const float4*>(&g_z[n*CSH + jb]);
    float4 nv = *reinterpret_cast<const float4*>(&g_num[n*CSH + jb]);
    float4 o;
    o.x = xv.x + (zv.x > 0.f ? nv.x / zv.x : 0.f);
    o.y = xv.y + (zv.y > 0.f ? nv.y / zv.y : 0.f);
    o.z = xv.z + (zv.z > 0.f ? nv.z / zv.z : 0.f);
    o.w = xv.w + (zv.w > 0.f ? nv.w / zv.w : 0.f);
    reinterpret_cast<float4*>(out)[i] = o;
}

// ---------------- launch ----------------
extern "C" void kernel_launch(void* const* d_in, const int* in_sizes, int n_in,
                              void* d_out, int out_size) {
    (void)in_sizes; (void)n_in; (void)out_size;
    const float* x       = (const float*)d_in[0];
    const float* x_knn   = (const float*)d_in[1];
    const int*   knn_idx = (const int*)  d_in[2];
    const float* p_r     = (const float*)d_in[3];
    const float* W_lin   = (const float*)d_in[4];
    const float* b_lin   = (const float*)d_in[5];
    const float* W_x     = (const float*)d_in[6];
    const float* b_x     = (const float*)d_in[7];
    const float* W_p1    = (const float*)d_in[8];
    const float* gamma   = (const float*)d_in[9];
    const float* beta    = (const float*)d_in[10];
    const float* W_p2    = (const float*)d_in[11];
    const float* b_p2    = (const float*)d_in[12];

    cudaFuncSetAttribute(main_kernel, cudaFuncAttributeMaxDynamicSharedMemorySize,
                         (int)sizeof(SmemT));

    init_kernel<<<(NPTS*CSH + 255)/256, 256>>>();
    stats_kernel<<<592, 256>>>(p_r, W_p1);
    consts_kernel<<<1, 64>>>(W_lin, b_lin, W_p2, b_p2, W_p1, gamma, beta);
    main_kernel<<<MROWS/128, 256, sizeof(SmemT)>>>(x_knn, knn_idx, p_r, W_lin, W_x, b_x);
    out_kernel<<<(NPTS*32 + 255)/256, 256>>>(x, (float*)d_out);
}

// round 4
// speedup vs baseline: 1.8064x; 1.8064x over previous
#include <cuda_runtime.h>
#include <cuda_bf16.h>
#include <cstdint>

#define NPTS   50000
#define KNN    16
#define CH     128
#define CSH    16
#define MROWS  (NPTS*KNN)
#define BN_EPS 1e-5f

// ---------------- device scratch (no allocations allowed) ----------------
__device__ __align__(16) float g_z[NPTS*CSH];
__device__ __align__(16) float g_num[NPTS*CSH];
__device__ float g_stats[6];   // [0..2] sum(h), [3..5] sum(h^2)
__device__ float g_M[3*CSH];   // folded p-path matrix (3 x 16)
__device__ float g_Bc[CSH];    // folded bias for s
__device__ float g_wf[9];      // BN-folded W_p1 (gamma*rstd absorbed)
__device__ float g_gb[3];      // BN shift (beta - mu*scale)

// ---------------- init: zero accumulators ----------------
__global__ void init_kernel() {
    int i = blockIdx.x*blockDim.x + threadIdx.x;
    if (i < NPTS*CSH) { g_z[i] = 0.f; g_num[i] = 0.f; }
    if (i < 6) g_stats[i] = 0.f;
}

// ---------------- BN stats over h = p_r @ W_p1^T ----------------
__global__ void stats_kernel(const float* __restrict__ p_r,
                             const float* __restrict__ W_p1) {
    float w0=W_p1[0],w1=W_p1[1],w2=W_p1[2],w3=W_p1[3],w4=W_p1[4],
          w5=W_p1[5],w6=W_p1[6],w7=W_p1[7],w8=W_p1[8];
    float s0=0,s1=0,s2=0,q0=0,q1=0,q2=0;
    int stride = gridDim.x*blockDim.x;
    for (int i = blockIdx.x*blockDim.x + threadIdx.x; i < MROWS; i += stride) {
        float p0=p_r[3*i+0], p1=p_r[3*i+1], p2=p_r[3*i+2];
        float h0 = p0*w0 + p1*w1 + p2*w2;
        float h1 = p0*w3 + p1*w4 + p2*w5;
        float h2 = p0*w6 + p1*w7 + p2*w8;
        s0+=h0; q0+=h0*h0; s1+=h1; q1+=h1*h1; s2+=h2; q2+=h2*h2;
    }
    #pragma unroll
    for (int o=16;o>0;o>>=1){
        s0+=__shfl_down_sync(0xffffffffu,s0,o);
        s1+=__shfl_down_sync(0xffffffffu,s1,o);
        s2+=__shfl_down_sync(0xffffffffu,s2,o);
        q0+=__shfl_down_sync(0xffffffffu,q0,o);
        q1+=__shfl_down_sync(0xffffffffu,q1,o);
        q2+=__shfl_down_sync(0xffffffffu,q2,o);
    }
    __shared__ float red[8][6];
    int wid = threadIdx.x>>5, lid = threadIdx.x&31;
    if (lid==0){ red[wid][0]=s0; red[wid][1]=s1; red[wid][2]=s2;
                 red[wid][3]=q0; red[wid][4]=q1; red[wid][5]=q2; }
    __syncthreads();
    if (threadIdx.x < 6) {
        float a = 0.f;
        #pragma unroll
        for (int w=0; w<8; w++) a += red[w][threadIdx.x];
        atomicAdd(&g_stats[threadIdx.x], a);
    }
}

// ---------------- fold constants ----------------
__global__ void consts_kernel(const float* __restrict__ W_lin,
                              const float* __restrict__ b_lin,
                              const float* __restrict__ W_p2,
                              const float* __restrict__ b_p2,
                              const float* __restrict__ W_p1,
                              const float* __restrict__ gamma,
                              const float* __restrict__ beta) {
    int tid = threadIdx.x;
    if (tid < 3) {
        float inv = 1.f / (float)MROWS;
        float mu  = g_stats[tid] * inv;
        float var = g_stats[3+tid] * inv - mu*mu;
        float gs  = gamma[tid] * rsqrtf(var + BN_EPS);
        g_gb[tid] = beta[tid] - mu*gs;
        #pragma unroll
        for (int c=0;c<3;c++) g_wf[tid*3+c] = gs * W_p1[tid*3+c];
    }
    if (tid < 48) {
        int a = tid >> 4, j = tid & 15;
        float m = 0.f;
        for (int c=0;c<CH;c++) m += W_p2[c*3+a] * W_lin[j*256+c];
        g_M[a*CSH + j] = m;
    }
    if (tid >= 48 && tid < 64) {
        int j = tid - 48;
        float b = b_lin[j];
        for (int c=0;c<CH;c++) b += b_p2[c] * W_lin[j*256+c];
        g_Bc[j] = b;
    }
}

// ================= mma.sync helpers =================
#define ASTRIDE 272   // bytes per A row (136 bf16: 128 + 8 pad) -> ldmatrix conflict-free
#define BSTRIDE 264   // bytes per B row (132 bf16)

#define A_HI_OFF 0
#define A_LO_OFF 34816          // 128*272
#define B_HI_OFF 69632
#define B_LO_OFF 78080          // +32*264=8448
#define HS_OFF   86528          // 128 * 16B
#define SMEM_DYN 88576

__device__ __forceinline__ void ldsm4(uint32_t& r0, uint32_t& r1, uint32_t& r2,
                                      uint32_t& r3, uint32_t addr) {
    asm volatile("ldmatrix.sync.aligned.m8n8.x4.shared.b16 {%0,%1,%2,%3}, [%4];"
                 : "=r"(r0), "=r"(r1), "=r"(r2), "=r"(r3) : "r"(addr));
}

__device__ __forceinline__ void mma16816(float* c, const uint32_t* a,
                                         uint32_t b0, uint32_t b1) {
    asm volatile("mma.sync.aligned.m16n8k16.row.col.f32.bf16.bf16.f32 "
                 "{%0,%1,%2,%3}, {%4,%5,%6,%7}, {%8,%9}, {%0,%1,%2,%3};"
                 : "+f"(c[0]), "+f"(c[1]), "+f"(c[2]), "+f"(c[3])
                 : "r"(a[0]), "r"(a[1]), "r"(a[2]), "r"(a[3]), "r"(b0), "r"(b1));
}

struct __align__(8) BF4 { __nv_bfloat162 a, b; };

// ---------------- fused main kernel (mma.sync bf16, split-precision) ----------------
__global__ void __launch_bounds__(128) main_kernel(
    const float* __restrict__ x_knn,
    const int*   __restrict__ knn_idx,
    const float* __restrict__ p_r,
    const float* __restrict__ W_lin,
    const float* __restrict__ W_x,
    const float* __restrict__ b_x)
{
    extern __shared__ char smp[];
    uint32_t sb;
    asm("{ .reg .u64 t; cvta.to.shared.u64 t, %1; cvt.u32.u64 %0, t; }"
        : "=r"(sb) : "l"(smp));

    const int tid  = threadIdx.x;
    const int lane = tid & 31;
    const int wid  = tid >> 5;
    const int base = blockIdx.x * 128;

    // ---- stage A: x_knn -> bf16 hi/lo, row-major padded ----
    const float4* src = reinterpret_cast<const float4*>(x_knn) + (size_t)base * 32;
    #pragma unroll
    for (int i = 0; i < 32; i++) {
        int q = i*128 + tid;
        int row = q >> 5, kk4 = q & 31;
        float4 v = src[q];
        __nv_bfloat16 hx = __float2bfloat16_rn(v.x);
        __nv_bfloat16 hy = __float2bfloat16_rn(v.y);
        __nv_bfloat16 hz = __float2bfloat16_rn(v.z);
        __nv_bfloat16 hw = __float2bfloat16_rn(v.w);
        BF4 hv, lv;
        hv.a.x = hx; hv.a.y = hy; hv.b.x = hz; hv.b.y = hw;
        lv.a.x = __float2bfloat16_rn(v.x - __bfloat162float(hx));
        lv.a.y = __float2bfloat16_rn(v.y - __bfloat162float(hy));
        lv.b.x = __float2bfloat16_rn(v.z - __bfloat162float(hz));
        lv.b.y = __float2bfloat16_rn(v.w - __bfloat162float(hw));
        uint32_t off = (uint32_t)row*ASTRIDE + (uint32_t)kk4*8;
        *reinterpret_cast<BF4*>(smp + A_HI_OFF + off) = hv;
        *reinterpret_cast<BF4*>(smp + A_LO_OFF + off) = lv;
    }

    // ---- stage B: rows 0..15 = W_lin[:,128+k] (s), rows 16..31 = W_x (v) ----
    #pragma unroll
    for (int i = 0; i < 32; i++) {
        int e = i*128 + tid;
        int n = e >> 7, k = e & 127;
        float val = (n < 16) ? W_lin[n*256 + 128 + k] : W_x[(n-16)*128 + k];
        __nv_bfloat16 hi = __float2bfloat16_rn(val);
        __nv_bfloat16 lo = __float2bfloat16_rn(val - __bfloat162float(hi));
        uint32_t off = (uint32_t)n*BSTRIDE + (uint32_t)k*2;
        *reinterpret_cast<__nv_bfloat16*>(smp + B_HI_OFF + off) = hi;
        *reinterpret_cast<__nv_bfloat16*>(smp + B_LO_OFF + off) = lo;
    }

    // ---- stage hs: per-row BN'd relu'd h ----
    {
        int r = base + tid;
        float p0 = p_r[3*r+0], p1 = p_r[3*r+1], p2 = p_r[3*r+2];
        float4 h;
        h.x = fmaxf(p0*g_wf[0] + p1*g_wf[1] + p2*g_wf[2] + g_gb[0], 0.f);
        h.y = fmaxf(p0*g_wf[3] + p1*g_wf[4] + p2*g_wf[5] + g_gb[1], 0.f);
        h.z = fmaxf(p0*g_wf[6] + p1*g_wf[7] + p2*g_wf[8] + g_gb[2], 0.f);
        h.w = 0.f;
        *reinterpret_cast<float4*>(smp + HS_OFF + tid*16) = h;
    }
    __syncthreads();

    // ---- warp-level MMA: warp w computes rows 32w..32w+31, all 32 cols ----
    const uint32_t warp_row = wid * 32;
    float acc[2][4][4];   // [m-tile][n-tile: 0,1 s / 2,3 v][reg]
    #pragma unroll
    for (int m=0;m<2;m++)
        #pragma unroll
        for (int n=0;n<4;n++)
            #pragma unroll
            for (int r=0;r<4;r++) acc[m][n][r] = 0.f;

    const uint32_t aOff = (warp_row + (lane & 15)) * ASTRIDE + (lane >> 4) * 16;
    const uint32_t bRow = (uint32_t)(lane >> 2) * BSTRIDE + (uint32_t)(lane & 3) * 4;

    #pragma unroll
    for (int ks = 0; ks < 8; ks++) {
        const uint32_t kB = ks * 32;    // 16 cols * 2B
        uint32_t ah[2][4], al[2][4];
        ldsm4(ah[0][0], ah[0][1], ah[0][2], ah[0][3], sb + A_HI_OFF + aOff + kB);
        ldsm4(ah[1][0], ah[1][1], ah[1][2], ah[1][3], sb + A_HI_OFF + aOff + 16*ASTRIDE + kB);
        ldsm4(al[0][0], al[0][1], al[0][2], al[0][3], sb + A_LO_OFF + aOff + kB);
        ldsm4(al[1][0], al[1][1], al[1][2], al[1][3], sb + A_LO_OFF + aOff + 16*ASTRIDE + kB);
        #pragma unroll
        for (int nt = 0; nt < 4; nt++) {
            uint32_t off = bRow + (uint32_t)nt * 8 * BSTRIDE + kB;
            uint32_t bh0 = *reinterpret_cast<const uint32_t*>(smp + B_HI_OFF + off);
            uint32_t bh1 = *reinterpret_cast<const uint32_t*>(smp + B_HI_OFF + off + 16);
            uint32_t bl0 = *reinterpret_cast<const uint32_t*>(smp + B_LO_OFF + off);
            uint32_t bl1 = *reinterpret_cast<const uint32_t*>(smp + B_LO_OFF + off + 16);
            mma16816(acc[0][nt], ah[0], bh0, bh1);
            mma16816(acc[1][nt], ah[1], bh0, bh1);
            mma16816(acc[0][nt], al[0], bh0, bh1);
            mma16816(acc[1][nt], al[1], bh0, bh1);
            mma16816(acc[0][nt], ah[0], bl0, bl1);
            mma16816(acc[1][nt], ah[1], bl0, bl1);
        }
    }

    // ---- epilogue: lane-local, red.v2 scatters ----
    const int l4 = lane >> 2;
    const int j0 = 2 * (lane & 3);
    float Bc_[4], bx_[4], M0[4], M1[4], M2[4];
    #pragma unroll
    for (int cc = 0; cc < 4; cc++) {
        int j = (cc >> 1) * 8 + j0 + (cc & 1);
        Bc_[cc] = g_Bc[j];  bx_[cc] = b_x[j];
        M0[cc] = g_M[j];  M1[cc] = g_M[16+j];  M2[cc] = g_M[32+j];
    }

    #pragma unroll
    for (int mt = 0; mt < 2; mt++) {
        #pragma unroll
        for (int hh = 0; hh < 2; hh++) {
            int row = warp_row + 16*mt + 8*hh + l4;
            float4 hv = *reinterpret_cast<const float4*>(smp + HS_OFF + row*16);
            int idx = knn_idx[base + row];
            float e[4], w[4];
            #pragma unroll
            for (int cc = 0; cc < 4; cc++) {
                float s = acc[mt][cc >> 1][2*hh + (cc & 1)];
                float v = acc[mt][2 + (cc >> 1)][2*hh + (cc & 1)];
                float sv = s + Bc_[cc] + hv.x*M0[cc] + hv.y*M1[cc] + hv.z*M2[cc];
                e[cc] = __expf(fmaxf(sv, 0.f));
                w[cc] = fmaxf(v + bx_[cc], 0.f) * e[cc];
            }
            float* zp = &g_z[idx*CSH];
            float* np = &g_num[idx*CSH];
            asm volatile("red.global.add.v2.f32 [%0], {%1,%2};"
                         :: "l"(zp + j0),     "f"(e[0]), "f"(e[1]) : "memory");
            asm volatile("red.global.add.v2.f32 [%0], {%1,%2};"
                         :: "l"(zp + 8 + j0), "f"(e[2]), "f"(e[3]) : "memory");
            asm volatile("red.global.add.v2.f32 [%0], {%1,%2};"
                         :: "l"(np + j0),     "f"(w[0]), "f"(w[1]) : "memory");
            asm volatile("red.global.add.v2.f32 [%0], {%1,%2};"
                         :: "l"(np + 8 + j0), "f"(w[2]), "f"(w[3]) : "memory");
        }
    }
}

// ---------------- output: x + tile(num/z, 8) ----------------
__global__ void out_kernel(const float* __restrict__ x, float* __restrict__ out) {
    int i = blockIdx.x*blockDim.x + threadIdx.x;
    if (i >= NPTS*32) return;
    int n = i >> 5, q = i & 31;
    int jb = (q & 3) * 4;
    float4 xv = reinterpret_cast<const float4*>(x)[i];
    float4 zv = *reinterpret_cast<const float4*>(&g_z[n*CSH + jb]);
    float4 nv = *reinterpret_cast<const float4*>(&g_num[n*CSH + jb]);
    float4 o;
    o.x = xv.x + (zv.x > 0.f ? nv.x / zv.x : 0.f);
    o.y = xv.y + (zv.y > 0.f ? nv.y / zv.y : 0.f);
    o.z = xv.z + (zv.z > 0.f ? nv.z / zv.z : 0.f);
    o.w = xv.w + (zv.w > 0.f ? nv.w / zv.w : 0.f);
    reinterpret_cast<float4*>(out)[i] = o;
}

// ---------------- launch ----------------
extern "C" void kernel_launch(void* const* d_in, const int* in_sizes, int n_in,
                              void* d_out, int out_size) {
    (void)in_sizes; (void)n_in; (void)out_size;
    const float* x       = (const float*)d_in[0];
    const float* x_knn   = (const float*)d_in[1];
    const int*   knn_idx = (const int*)  d_in[2];
    const float* p_r     = (const float*)d_in[3];
    const float* W_lin   = (const float*)d_in[4];
    const float* b_lin   = (const float*)d_in[5];
    const float* W_x     = (const float*)d_in[6];
    const float* b_x     = (const float*)d_in[7];
    const float* W_p1    = (const float*)d_in[8];
    const float* gamma   = (const float*)d_in[9];
    const float* beta    = (const float*)d_in[10];
    const float* W_p2    = (const float*)d_in[11];
    const float* b_p2    = (const float*)d_in[12];

    cudaFuncSetAttribute(main_kernel, cudaFuncAttributeMaxDynamicSharedMemorySize, SMEM_DYN);

    init_kernel<<<(NPTS*CSH + 255)/256, 256>>>();
    stats_kernel<<<592, 256>>>(p_r, W_p1);
    consts_kernel<<<1, 64>>>(W_lin, b_lin, W_p2, b_p2, W_p1, gamma, beta);
    main_kernel<<<MROWS/128, 128, SMEM_DYN>>>(x_knn, knn_idx, p_r, W_lin, W_x, b_x);
    out_kernel<<<(NPTS*32 + 255)/256, 256>>>(x, (float*)d_out);
}

// round 5
// speedup vs baseline: 2.0889x; 1.1564x over previous
#include <cuda_runtime.h>
#include <cuda_bf16.h>
#include <cstdint>

#define NPTS   50000
#define KNN    16
#define CH     128
#define CSH    16
#define MROWS  (NPTS*KNN)
#define BN_EPS 1e-5f

// ---------------- device scratch (no allocations allowed) ----------------
__device__ __align__(16) float g_z[NPTS*CSH];
__device__ __align__(16) float g_num[NPTS*CSH];
__device__ float g_stats[6];   // [0..2] sum(h), [3..5] sum(h^2)
__device__ float g_M[3*CSH];   // folded p-path matrix (3 x 16)
__device__ float g_Bc[CSH];    // folded bias for s
__device__ float g_wf[9];      // BN-folded W_p1 (gamma*rstd absorbed)
__device__ float g_gb[3];      // BN shift (beta - mu*scale)

// ---------------- init: zero accumulators ----------------
__global__ void init_kernel() {
    int i = blockIdx.x*blockDim.x + threadIdx.x;
    if (i < NPTS*CSH) { g_z[i] = 0.f; g_num[i] = 0.f; }
    if (i < 6) g_stats[i] = 0.f;
}

// ---------------- BN stats over h = p_r @ W_p1^T ----------------
__global__ void stats_kernel(const float* __restrict__ p_r,
                             const float* __restrict__ W_p1) {
    float w0=W_p1[0],w1=W_p1[1],w2=W_p1[2],w3=W_p1[3],w4=W_p1[4],
          w5=W_p1[5],w6=W_p1[6],w7=W_p1[7],w8=W_p1[8];
    float s0=0,s1=0,s2=0,q0=0,q1=0,q2=0;
    int stride = gridDim.x*blockDim.x;
    for (int i = blockIdx.x*blockDim.x + threadIdx.x; i < MROWS; i += stride) {
        float p0=p_r[3*i+0], p1=p_r[3*i+1], p2=p_r[3*i+2];
        float h0 = p0*w0 + p1*w1 + p2*w2;
        float h1 = p0*w3 + p1*w4 + p2*w5;
        float h2 = p0*w6 + p1*w7 + p2*w8;
        s0+=h0; q0+=h0*h0; s1+=h1; q1+=h1*h1; s2+=h2; q2+=h2*h2;
    }
    #pragma unroll
    for (int o=16;o>0;o>>=1){
        s0+=__shfl_down_sync(0xffffffffu,s0,o);
        s1+=__shfl_down_sync(0xffffffffu,s1,o);
        s2+=__shfl_down_sync(0xffffffffu,s2,o);
        q0+=__shfl_down_sync(0xffffffffu,q0,o);
        q1+=__shfl_down_sync(0xffffffffu,q1,o);
        q2+=__shfl_down_sync(0xffffffffu,q2,o);
    }
    __shared__ float red[8][6];
    int wid = threadIdx.x>>5, lid = threadIdx.x&31;
    if (lid==0){ red[wid][0]=s0; red[wid][1]=s1; red[wid][2]=s2;
                 red[wid][3]=q0; red[wid][4]=q1; red[wid][5]=q2; }
    __syncthreads();
    if (threadIdx.x < 6) {
        float a = 0.f;
        #pragma unroll
        for (int w=0; w<8; w++) a += red[w][threadIdx.x];
        atomicAdd(&g_stats[threadIdx.x], a);
    }
}

// ---------------- fold constants ----------------
__global__ void consts_kernel(const float* __restrict__ W_lin,
                              const float* __restrict__ b_lin,
                              const float* __restrict__ W_p2,
                              const float* __restrict__ b_p2,
                              const float* __restrict__ W_p1,
                              const float* __restrict__ gamma,
                              const float* __restrict__ beta) {
    int tid = threadIdx.x;
    if (tid < 3) {
        float inv = 1.f / (float)MROWS;
        float mu  = g_stats[tid] * inv;
        float var = g_stats[3+tid] * inv - mu*mu;
        float gs  = gamma[tid] * rsqrtf(var + BN_EPS);
        g_gb[tid] = beta[tid] - mu*gs;
        #pragma unroll
        for (int c=0;c<3;c++) g_wf[tid*3+c] = gs * W_p1[tid*3+c];
    }
    if (tid < 48) {
        int a = tid >> 4, j = tid & 15;
        float m = 0.f;
        for (int c=0;c<CH;c++) m += W_p2[c*3+a] * W_lin[j*256+c];
        g_M[a*CSH + j] = m;
    }
    if (tid >= 48 && tid < 64) {
        int j = tid - 48;
        float b = b_lin[j];
        for (int c=0;c<CH;c++) b += b_p2[c] * W_lin[j*256+c];
        g_Bc[j] = b;
    }
}

// ================= mma.sync helpers =================
#define ASTRIDE 144   // bytes per A row half (64 bf16 = 128B + 16B pad) -> conflict-free
#define BSTRIDE 264   // bytes per B row (132 bf16)

#define A_HI_OFF 0
#define A_LO_OFF 18432          // 128*144
#define B_HI_OFF 36864
#define B_LO_OFF 45312          // +32*264=8448
#define HS_OFF   53760          // 128 * 16B
#define SMEM_DYN 55808

__device__ __forceinline__ void ldsm4(uint32_t& r0, uint32_t& r1, uint32_t& r2,
                                      uint32_t& r3, uint32_t addr) {
    asm volatile("ldmatrix.sync.aligned.m8n8.x4.shared.b16 {%0,%1,%2,%3}, [%4];"
                 : "=r"(r0), "=r"(r1), "=r"(r2), "=r"(r3) : "r"(addr));
}

__device__ __forceinline__ void mma16816(float* c, const uint32_t* a,
                                         uint32_t b0, uint32_t b1) {
    asm volatile("mma.sync.aligned.m16n8k16.row.col.f32.bf16.bf16.f32 "
                 "{%0,%1,%2,%3}, {%4,%5,%6,%7}, {%8,%9}, {%0,%1,%2,%3};"
                 : "+f"(c[0]), "+f"(c[1]), "+f"(c[2]), "+f"(c[3])
                 : "r"(a[0]), "r"(a[1]), "r"(a[2]), "r"(a[3]), "r"(b0), "r"(b1));
}

struct __align__(8) BF4 { __nv_bfloat162 a, b; };

// ---------------- fused main kernel (mma.sync bf16, K-split for occupancy) ----------------
__global__ void __launch_bounds__(128, 4) main_kernel(
    const float* __restrict__ x_knn,
    const int*   __restrict__ knn_idx,
    const float* __restrict__ p_r,
    const float* __restrict__ W_lin,
    const float* __restrict__ W_x,
    const float* __restrict__ b_x)
{
    extern __shared__ char smp[];
    uint32_t sb;
    asm("{ .reg .u64 t; cvta.to.shared.u64 t, %1; cvt.u32.u64 %0, t; }"
        : "=r"(sb) : "l"(smp));

    const int tid  = threadIdx.x;
    const int lane = tid & 31;
    const int wid  = tid >> 5;
    const int base = blockIdx.x * 128;

    const float4* src = reinterpret_cast<const float4*>(x_knn) + (size_t)base * 32;

    // ---- stage A half 0 (K cols 0..63) ----
    #pragma unroll
    for (int i = 0; i < 16; i++) {
        int q = i*128 + tid;            // 0..2047
        int row = q >> 4, kk4 = q & 15;
        float4 v = src[row*32 + kk4];
        __nv_bfloat16 hx = __float2bfloat16_rn(v.x);
        __nv_bfloat16 hy = __float2bfloat16_rn(v.y);
        __nv_bfloat16 hz = __float2bfloat16_rn(v.z);
        __nv_bfloat16 hw = __float2bfloat16_rn(v.w);
        BF4 hv, lv;
        hv.a.x = hx; hv.a.y = hy; hv.b.x = hz; hv.b.y = hw;
        lv.a.x = __float2bfloat16_rn(v.x - __bfloat162float(hx));
        lv.a.y = __float2bfloat16_rn(v.y - __bfloat162float(hy));
        lv.b.x = __float2bfloat16_rn(v.z - __bfloat162float(hz));
        lv.b.y = __float2bfloat16_rn(v.w - __bfloat162float(hw));
        uint32_t off = (uint32_t)row*ASTRIDE + (uint32_t)kk4*8;
        *reinterpret_cast<BF4*>(smp + A_HI_OFF + off) = hv;
        *reinterpret_cast<BF4*>(smp + A_LO_OFF + off) = lv;
    }

    // ---- stage B (full K): rows 0..15 = W_lin[:,128+k] (s), rows 16..31 = W_x (v) ----
    #pragma unroll
    for (int i = 0; i < 32; i++) {
        int e = i*128 + tid;
        int n = e >> 7, k = e & 127;
        float val = (n < 16) ? W_lin[n*256 + 128 + k] : W_x[(n-16)*128 + k];
        __nv_bfloat16 hi = __float2bfloat16_rn(val);
        __nv_bfloat16 lo = __float2bfloat16_rn(val - __bfloat162float(hi));
        uint32_t off = (uint32_t)n*BSTRIDE + (uint32_t)k*2;
        *reinterpret_cast<__nv_bfloat16*>(smp + B_HI_OFF + off) = hi;
        *reinterpret_cast<__nv_bfloat16*>(smp + B_LO_OFF + off) = lo;
    }

    // ---- stage hs: per-row BN'd relu'd h ----
    {
        int r = base + tid;
        float p0 = p_r[3*r+0], p1 = p_r[3*r+1], p2 = p_r[3*r+2];
        float4 h;
        h.x = fmaxf(p0*g_wf[0] + p1*g_wf[1] + p2*g_wf[2] + g_gb[0], 0.f);
        h.y = fmaxf(p0*g_wf[3] + p1*g_wf[4] + p2*g_wf[5] + g_gb[1], 0.f);
        h.z = fmaxf(p0*g_wf[6] + p1*g_wf[7] + p2*g_wf[8] + g_gb[2], 0.f);
        h.w = 0.f;
        *reinterpret_cast<float4*>(smp + HS_OFF + tid*16) = h;
    }
    __syncthreads();

    // ---- MMA accumulators (persist over both K halves) ----
    const uint32_t warp_row = wid * 32;
    float acc[2][4][4];   // [m-tile][n-tile: 0,1 s / 2,3 v][reg]
    #pragma unroll
    for (int m=0;m<2;m++)
        #pragma unroll
        for (int n=0;n<4;n++)
            #pragma unroll
            for (int r=0;r<4;r++) acc[m][n][r] = 0.f;

    const uint32_t aOff = (warp_row + (lane & 15)) * ASTRIDE + (lane >> 4) * 16;
    const uint32_t bRow = (uint32_t)(lane >> 2) * BSTRIDE + (uint32_t)(lane & 3) * 4;

    #pragma unroll
    for (int half = 0; half < 2; half++) {
        // MMA over this half's 4 k-steps
        #pragma unroll
        for (int ks = 0; ks < 4; ks++) {
            const uint32_t kA = ks * 32;               // within-half A byte offset
            const uint32_t kB = half * 128 + ks * 32;  // full-K B byte offset
            uint32_t ah[2][4], al[2][4];
            ldsm4(ah[0][0], ah[0][1], ah[0][2], ah[0][3], sb + A_HI_OFF + aOff + kA);
            ldsm4(ah[1][0], ah[1][1], ah[1][2], ah[1][3], sb + A_HI_OFF + aOff + 16*ASTRIDE + kA);
            ldsm4(al[0][0], al[0][1], al[0][2], al[0][3], sb + A_LO_OFF + aOff + kA);
            ldsm4(al[1][0], al[1][1], al[1][2], al[1][3], sb + A_LO_OFF + aOff + 16*ASTRIDE + kA);
            #pragma unroll
            for (int nt = 0; nt < 4; nt++) {
                uint32_t off = bRow + (uint32_t)nt * 8 * BSTRIDE + kB;
                uint32_t bh0 = *reinterpret_cast<const uint32_t*>(smp + B_HI_OFF + off);
                uint32_t bh1 = *reinterpret_cast<const uint32_t*>(smp + B_HI_OFF + off + 16);
                uint32_t bl0 = *reinterpret_cast<const uint32_t*>(smp + B_LO_OFF + off);
                uint32_t bl1 = *reinterpret_cast<const uint32_t*>(smp + B_LO_OFF + off + 16);
                mma16816(acc[0][nt], ah[0], bh0, bh1);
                mma16816(acc[1][nt], ah[1], bh0, bh1);
                mma16816(acc[0][nt], al[0], bh0, bh1);
                mma16816(acc[1][nt], al[1], bh0, bh1);
                mma16816(acc[0][nt], ah[0], bl0, bl1);
                mma16816(acc[1][nt], ah[1], bl0, bl1);
            }
        }

        if (half == 0) {
            // restage A with K cols 64..127
            __syncthreads();
            #pragma unroll
            for (int i = 0; i < 16; i++) {
                int q = i*128 + tid;
                int row = q >> 4, kk4 = q & 15;
                float4 v = src[row*32 + 16 + kk4];
                __nv_bfloat16 hx = __float2bfloat16_rn(v.x);
                __nv_bfloat16 hy = __float2bfloat16_rn(v.y);
                __nv_bfloat16 hz = __float2bfloat16_rn(v.z);
                __nv_bfloat16 hw = __float2bfloat16_rn(v.w);
                BF4 hv, lv;
                hv.a.x = hx; hv.a.y = hy; hv.b.x = hz; hv.b.y = hw;
                lv.a.x = __float2bfloat16_rn(v.x - __bfloat162float(hx));
                lv.a.y = __float2bfloat16_rn(v.y - __bfloat162float(hy));
                lv.b.x = __float2bfloat16_rn(v.z - __bfloat162float(hz));
                lv.b.y = __float2bfloat16_rn(v.w - __bfloat162float(hw));
                uint32_t off = (uint32_t)row*ASTRIDE + (uint32_t)kk4*8;
                *reinterpret_cast<BF4*>(smp + A_HI_OFF + off) = hv;
                *reinterpret_cast<BF4*>(smp + A_LO_OFF + off) = lv;
            }
            __syncthreads();
        }
    }

    // ---- epilogue: lane-local, red.v2 scatters ----
    const int l4 = lane >> 2;
    const int j0 = 2 * (lane & 3);
    float Bc_[4], bx_[4], M0[4], M1[4], M2[4];
    #pragma unroll
    for (int cc = 0; cc < 4; cc++) {
        int j = (cc >> 1) * 8 + j0 + (cc & 1);
        Bc_[cc] = g_Bc[j];  bx_[cc] = b_x[j];
        M0[cc] = g_M[j];  M1[cc] = g_M[16+j];  M2[cc] = g_M[32+j];
    }

    #pragma unroll
    for (int mt = 0; mt < 2; mt++) {
        #pragma unroll
        for (int hh = 0; hh < 2; hh++) {
            int row = warp_row + 16*mt + 8*hh + l4;
            float4 hv = *reinterpret_cast<const float4*>(smp + HS_OFF + row*16);
            int idx = knn_idx[base + row];
            float e[4], w[4];
            #pragma unroll
            for (int cc = 0; cc < 4; cc++) {
                float s = acc[mt][cc >> 1][2*hh + (cc & 1)];
                float v = acc[mt][2 + (cc >> 1)][2*hh + (cc & 1)];
                float sv = s + Bc_[cc] + hv.x*M0[cc] + hv.y*M1[cc] + hv.z*M2[cc];
                e[cc] = __expf(fmaxf(sv, 0.f));
                w[cc] = fmaxf(v + bx_[cc], 0.f) * e[cc];
            }
            float* zp = &g_z[idx*CSH];
            float* np = &g_num[idx*CSH];
            asm volatile("red.global.add.v2.f32 [%0], {%1,%2};"
                         :: "l"(zp + j0),     "f"(e[0]), "f"(e[1]) : "memory");
            asm volatile("red.global.add.v2.f32 [%0], {%1,%2};"
                         :: "l"(zp + 8 + j0), "f"(e[2]), "f"(e[3]) : "memory");
            asm volatile("red.global.add.v2.f32 [%0], {%1,%2};"
                         :: "l"(np + j0),     "f"(w[0]), "f"(w[1]) : "memory");
            asm volatile("red.global.add.v2.f32 [%0], {%1,%2};"
                         :: "l"(np + 8 + j0), "f"(w[2]), "f"(w[3]) : "memory");
        }
    }
}

// ---------------- output: x + tile(num/z, 8) ----------------
__global__ void out_kernel(const float* __restrict__ x, float* __restrict__ out) {
    int i = blockIdx.x*blockDim.x + threadIdx.x;
    if (i >= NPTS*32) return;
    int n = i >> 5, q = i & 31;
    int jb = (q & 3) * 4;
    float4 xv = reinterpret_cast<const float4*>(x)[i];
    float4 zv = *reinterpret_cast<const float4*>(&g_z[n*CSH + jb]);
    float4 nv = *reinterpret_cast<const float4*>(&g_num[n*CSH + jb]);
    float4 o;
    o.x = xv.x + (zv.x > 0.f ? nv.x / zv.x : 0.f);
    o.y = xv.y + (zv.y > 0.f ? nv.y / zv.y : 0.f);
    o.z = xv.z + (zv.z > 0.f ? nv.z / zv.z : 0.f);
    o.w = xv.w + (zv.w > 0.f ? nv.w / zv.w : 0.f);
    reinterpret_cast<float4*>(out)[i] = o;
}

// ---------------- launch ----------------
extern "C" void kernel_launch(void* const* d_in, const int* in_sizes, int n_in,
                              void* d_out, int out_size) {
    (void)in_sizes; (void)n_in; (void)out_size;
    const float* x       = (const float*)d_in[0];
    const float* x_knn   = (const float*)d_in[1];
    const int*   knn_idx = (const int*)  d_in[2];
    const float* p_r     = (const float*)d_in[3];
    const float* W_lin   = (const float*)d_in[4];
    const float* b_lin   = (const float*)d_in[5];
    const float* W_x     = (const float*)d_in[6];
    const float* b_x     = (const float*)d_in[7];
    const float* W_p1    = (const float*)d_in[8];
    const float* gamma   = (const float*)d_in[9];
    const float* beta    = (const float*)d_in[10];
    const float* W_p2    = (const float*)d_in[11];
    const float* b_p2    = (const float*)d_in[12];

    cudaFuncSetAttribute(main_kernel, cudaFuncAttributeMaxDynamicSharedMemorySize, SMEM_DYN);

    init_kernel<<<(NPTS*CSH + 255)/256, 256>>>();
    stats_kernel<<<592, 256>>>(p_r, W_p1);
    consts_kernel<<<1, 64>>>(W_lin, b_lin, W_p2, b_p2, W_p1, gamma, beta);
    main_kernel<<<MROWS/128, 128, SMEM_DYN>>>(x_knn, knn_idx, p_r, W_lin, W_x, b_x);
    out_kernel<<<(NPTS*32 + 255)/256, 256>>>(x, (float*)d_out);
}